// round 10
// baseline (speedup 1.0000x reference)
#include <cuda_runtime.h>
#include <cstdint>

#define BB 8
#define CC 256
#define HH 96
#define WW 96
#define HW (HH*WW)          // 9216
#define PATCH 21
#define NP    (PATCH*PATCH) // 441
#define HALFP 10
#define DILP 2
#define TROW 136            // 96 + 2*20 halo

#define NDOT  576           // dot units: 128 spatial floats x 256ch each
#define NGATH 768           // gather units: (b,y)
#define NPROD 288           // producer blocks
#define NCONS 304           // consumer blocks
#define GRID  (NPROD + NCONS)   // 592 = 148*4, all resident at occ 4

__device__ float g_D[BB * HW];     // 1.18 MB, L2-resident
__device__ int   g_cnt[BB];        // per-batch completed dot units (target 72)
__device__ int   g_done;           // finished consumer blocks (self-reset)

struct F8 { float4 a, b; };

// 32B load with L2 evict_last: inputs are re-read identically every graph
// replay -> pin them in L2. (ptxas only allows the hint on v8.b32 / v4.b64.)
__device__ __forceinline__ F8 ld8_last(const float* p) {
    uint32_t u0,u1,u2,u3,u4,u5,u6,u7;
    asm("ld.global.L2::evict_last.v8.b32 {%0,%1,%2,%3,%4,%5,%6,%7}, [%8];"
        : "=r"(u0),"=r"(u1),"=r"(u2),"=r"(u3),
          "=r"(u4),"=r"(u5),"=r"(u6),"=r"(u7) : "l"(p));
    F8 v;
    v.a.x=__uint_as_float(u0); v.a.y=__uint_as_float(u1);
    v.a.z=__uint_as_float(u2); v.a.w=__uint_as_float(u3);
    v.b.x=__uint_as_float(u4); v.b.y=__uint_as_float(u5);
    v.b.z=__uint_as_float(u6); v.b.w=__uint_as_float(u7);
    return v;
}

// 32B store with L2 evict_first: output is write-once, dead after replay.
__device__ __forceinline__ void st8_first(float* p, float4 a, float4 b) {
    asm volatile("st.global.L2::evict_first.v8.b32 [%0], {%1,%2,%3,%4,%5,%6,%7,%8};"
        :: "l"(p),
           "r"(__float_as_uint(a.x)),"r"(__float_as_uint(a.y)),
           "r"(__float_as_uint(a.z)),"r"(__float_as_uint(a.w)),
           "r"(__float_as_uint(b.x)),"r"(__float_as_uint(b.y)),
           "r"(__float_as_uint(b.z)),"r"(__float_as_uint(b.w)) : "memory");
}

__global__ void __launch_bounds__(256, 4) fused_kernel(
        const float* __restrict__ a,
        const float* __restrict__ b,
        float* __restrict__ out) {
    __shared__ union {
        float red[2048];             // 256 threads x float8 = 8KB
        float tile[PATCH * TROW];    // 11424 B
    } sm;

    const int tid = threadIdx.x;
    const int bid = blockIdx.x;

    if (bid < NPROD) {
        // ============ PRODUCER: dot units (16 lanes x float8, 16 cgroups) ===
        const int lane = tid & 15;         // float8 spatial lane (8 floats)
        const int cg   = tid >> 4;         // channel group 0..15 (16 ch each)
        const int c0   = cg * 16;

        float4* red4 = (float4*)sm.red;

        for (int u = bid; u < NDOT; u += NPROD) {
            const int bidx = u / 72;
            const int hw   = ((u * 128) % HW) + lane * 8;

            const float* __restrict__ A  = a + (size_t)bidx * CC * HW + hw;
            const float* __restrict__ Bp = b + (size_t)bidx * CC * HW + hw;

            float4 acc0 = make_float4(0.f,0.f,0.f,0.f);
            float4 acc1 = make_float4(0.f,0.f,0.f,0.f);
            #pragma unroll 4
            for (int c = 0; c < 16; ++c) {
                const size_t off = (size_t)(c0 + c) * HW;
                F8 x = ld8_last(A + off);
                F8 y = ld8_last(Bp + off);
                acc0.x = fmaf(x.a.x, y.a.x, acc0.x);
                acc0.y = fmaf(x.a.y, y.a.y, acc0.y);
                acc0.z = fmaf(x.a.z, y.a.z, acc0.z);
                acc0.w = fmaf(x.a.w, y.a.w, acc0.w);
                acc1.x = fmaf(x.b.x, y.b.x, acc1.x);
                acc1.y = fmaf(x.b.y, y.b.y, acc1.y);
                acc1.z = fmaf(x.b.z, y.b.z, acc1.z);
                acc1.w = fmaf(x.b.w, y.b.w, acc1.w);
            }

            red4[tid * 2]     = acc0;
            red4[tid * 2 + 1] = acc1;
            __syncthreads();

            // tree-reduce over the 16 channel groups (slot = tid)
            #pragma unroll
            for (int k = 8; k >= 1; k >>= 1) {
                if (cg < k) {
                    const int p2 = (tid + 16 * k) * 2;
                    float4 t0 = red4[p2], t1 = red4[p2 + 1];
                    float4 r0 = red4[tid * 2], r1 = red4[tid * 2 + 1];
                    r0.x += t0.x; r0.y += t0.y; r0.z += t0.z; r0.w += t0.w;
                    r1.x += t1.x; r1.y += t1.y; r1.z += t1.z; r1.w += t1.w;
                    red4[tid * 2] = r0; red4[tid * 2 + 1] = r1;
                }
                __syncthreads();
            }

            if (tid < 16) {
                float4* d4 = (float4*)(g_D + (size_t)u * 128 + tid * 8);
                d4[0] = red4[tid * 2];
                d4[1] = red4[tid * 2 + 1];
            }
            __syncthreads();                       // smem free before reuse
            if (tid == 0) {
                __threadfence();                   // publish g_D
                atomicAdd(&g_cnt[bidx], 1);
            }
        }
    } else {
        // ===================== CONSUMER: gather units =====================
        const float4* __restrict__ D4 = (const float4*)g_D;

        for (int g = bid - NPROD; g < NGATH; g += NCONS) {
            const int bb = g / HH;                 // batch
            const int y  = g - bb * HH;

            // zero tile while (possibly) waiting
            for (int i = tid; i < PATCH * TROW; i += 256) sm.tile[i] = 0.f;

            if (tid == 0) {
                volatile int* c = &g_cnt[bb];
                while (*c < 72) __nanosleep(100);
                __threadfence();                   // acquire
            }
            __syncthreads();

            // stage 21 candidate rows (+-20 col halo pre-zeroed)
            for (int i = tid; i < PATCH * 24; i += 256) {
                const int r  = i / 24;
                const int x4 = i - r * 24;
                const int sy = y + (r - HALFP) * DILP;
                if ((unsigned)sy < (unsigned)HH) {
                    float4 v = D4[(bb * HH + sy) * 24 + x4];
                    *(float4*)(sm.tile + r * TROW + 20 + x4 * 4) = v;
                }
            }
            __syncthreads();

            // emit 441 x 12 32B evict-first stores
            float* obase = out + ((size_t)bb * NP) * HW + y * WW;
            for (int i = tid; i < NP * 12; i += 256) {
                const int p  = i / 12;
                const int x8 = i - p * 12;
                const int py = p / PATCH;
                const int px = p - py * PATCH;

                const float2* sp =
                    (const float2*)(sm.tile + py * TROW + px * 2 + x8 * 8);
                float2 q0 = sp[0], q1 = sp[1], q2 = sp[2], q3 = sp[3];

                st8_first(obase + (size_t)p * HW + x8 * 8,
                          make_float4(q0.x, q0.y, q1.x, q1.y),
                          make_float4(q2.x, q2.y, q3.x, q3.y));
            }
            __syncthreads();                       // tile reuse safety
        }

        // ---- self-clean: last consumer block resets sync state for the
        // next graph replay (proven in R6/R8).
        if (tid == 0) {
            __threadfence();
            int d = atomicAdd(&g_done, 1);
            if (d == NCONS - 1) {
                #pragma unroll
                for (int i = 0; i < BB; ++i) g_cnt[i] = 0;
                g_done = 0;
                __threadfence();
            }
        }
    }
}

extern "C" void kernel_launch(void* const* d_in, const int* in_sizes, int n_in,
                              void* d_out, int out_size) {
    const float* in1 = (const float*)d_in[0];
    const float* in2 = (const float*)d_in[1];
    float* out = (float*)d_out;

    fused_kernel<<<GRID, 256>>>(in1, in2, out);
}